// round 6
// baseline (speedup 1.0000x reference)
#include <cuda_runtime.h>

#define FULL 0xffffffffu

// LISTA, latency-optimized v2: lane = g*16 + c*8 + i
//   i = code position (0..7), c = component (0 real / 1 imag),
//   g = column-in-warp (2 columns per warp). 16 blocks x 64 threads = 64 cols.
// Per-stage chain has only TWO dependent shuffle waves:
//   16 shfl (x broadcast, both components) -> 16-FMA dot (4 accumulators)
//   -> 4 shfl (z neighbors +-1,+-2) -> local conv1 at 3 positions -> conv2.
// No reduce wave (no h-split). Sign flip folded into weights (off-chain).
// W1[s]@y biases precomputed into registers before the sequential loop.

__global__ void __launch_bounds__(64, 1) lista_kernel(
    const float* __restrict__ y_real, const float* __restrict__ y_imag,
    const float* __restrict__ w1_real, const float* __restrict__ w1_imag,
    const float* __restrict__ w2_real, const float* __restrict__ w2_imag,
    const float* __restrict__ thr,
    const float* __restrict__ c1w, const float* __restrict__ c1b,
    const float* __restrict__ c2w, const float* __restrict__ c2b,
    float* __restrict__ out)
{
    __shared__ __align__(16) float s_c1w[16 * 12];   // 9 used + 3 pad / stage
    __shared__ __align__(16) float s_c1b[16 * 4];    // 3 used + 1 pad
    __shared__ __align__(16) float s_c2w[16 * 12];
    __shared__ __align__(16) float s_misc[16 * 2];   // {c2b[s], thr[s]}

    const int tid  = threadIdx.x;          // 0..63
    const int lane = tid & 31;
    const int i    = lane & 7;
    const int c    = (lane >> 3) & 1;
    const int b    = (int)blockIdx.x * 4 + (tid >> 4);   // batch column
    const float sgn = c ? 1.f : -1.f;   // z_r: -wi*x_i ; z_i: +wi*x_r

    // ---- one-time staging of conv params (padded, aligned) ----
    for (int k = tid; k < 192; k += 64) {
        int s = k / 12, r = k - s * 12;
        s_c1w[k] = (r < 9) ? c1w[s * 9 + r] : 0.f;
        s_c2w[k] = (r < 9) ? c2w[s * 9 + r] : 0.f;
    }
    {
        int s = tid >> 2, r = tid & 3;
        s_c1b[tid] = (r < 3) ? c1b[s * 3 + r] : 0.f;   // tid<64 covers all 64
    }
    if (tid < 32) {
        int s = tid >> 1;
        s_misc[tid] = (tid & 1) ? thr[s] : c2b[s];
    }

    // ---- y column: own component + sign-folded opposite component ----
    float yc[8], yos[8];
    {
        const float* yc_ptr = c ? y_imag : y_real;
        const float* yo_ptr = c ? y_real : y_imag;
        #pragma unroll
        for (int j = 0; j < 8; j++) {
            yc[j]  = yc_ptr[j * 64 + b];
            yos[j] = sgn * yo_ptr[j * 64 + b];
        }
    }

    // ---- precompute all 16 full stage biases (W1[s] y)_{i,c} ----
    float bias[16];
    #pragma unroll
    for (int s = 0; s < 16; s++) {
        const float4 wr0 = *(const float4*)(w1_real + s * 64 + i * 8);
        const float4 wr1 = *(const float4*)(w1_real + s * 64 + i * 8 + 4);
        const float4 wi0 = *(const float4*)(w1_imag + s * 64 + i * 8);
        const float4 wi1 = *(const float4*)(w1_imag + s * 64 + i * 8 + 4);
        float a0 = 0.f, a1 = 0.f, a2 = 0.f, a3 = 0.f;
        a0 = fmaf(wr0.x, yc[0], a0); a1 = fmaf(wi0.x, yos[0], a1);
        a2 = fmaf(wr0.y, yc[1], a2); a3 = fmaf(wi0.y, yos[1], a3);
        a0 = fmaf(wr0.z, yc[2], a0); a1 = fmaf(wi0.z, yos[2], a1);
        a2 = fmaf(wr0.w, yc[3], a2); a3 = fmaf(wi0.w, yos[3], a3);
        a0 = fmaf(wr1.x, yc[4], a0); a1 = fmaf(wi1.x, yos[4], a1);
        a2 = fmaf(wr1.y, yc[5], a2); a3 = fmaf(wi1.y, yos[5], a3);
        a0 = fmaf(wr1.z, yc[6], a0); a1 = fmaf(wi1.z, yos[6], a1);
        a2 = fmaf(wr1.w, yc[7], a2); a3 = fmaf(wi1.w, yos[7], a3);
        bias[s] = (a0 + a1) + (a2 + a3);
    }

    __syncthreads();

    // ---- init: x = soft(bias[0], thr[0]) ----
    float x;
    {
        const float t0 = s_misc[1];
        x = fmaxf(bias[0] - t0, 0.f) + fminf(bias[0] + t0, 0.f);
    }

    const int cbase = lane & 24;                     // g<<4 | c<<3 (own comp)
    const int obase = (lane & 16) | ((c ^ 1) << 3);  // opposite comp

    // ---- 16 sequential stages (fully unrolled) ----
    #pragma unroll
    for (int s = 0; s < 16; s++) {
        // single broadcast wave: both components, all 8 positions
        float xc[8], xo[8];
        #pragma unroll
        for (int j = 0; j < 8; j++) {
            xc[j] = __shfl_sync(FULL, x, cbase | j);
            xo[j] = __shfl_sync(FULL, x, obase | j);
        }

        // stage weights (x-independent: hoistable above/into the shfl wait)
        const float4 wr0 = *(const float4*)(w2_real + s * 64 + i * 8);
        const float4 wr1 = *(const float4*)(w2_real + s * 64 + i * 8 + 4);
        const float4 wi0 = *(const float4*)(w2_imag + s * 64 + i * 8);
        const float4 wi1 = *(const float4*)(w2_imag + s * 64 + i * 8 + 4);
        // sign folded into weights, off the x-dependent chain
        const float sw0 = sgn * wi0.x, sw1 = sgn * wi0.y;
        const float sw2 = sgn * wi0.z, sw3 = sgn * wi0.w;
        const float sw4 = sgn * wi1.x, sw5 = sgn * wi1.y;
        const float sw6 = sgn * wi1.z, sw7 = sgn * wi1.w;

        // full dot, 4 accumulators
        float a0 = bias[s], a1 = 0.f, a2 = 0.f, a3 = 0.f;
        a0 = fmaf(wr0.x, xc[0], a0); a1 = fmaf(sw0, xo[0], a1);
        a2 = fmaf(wr0.y, xc[1], a2); a3 = fmaf(sw1, xo[1], a3);
        a0 = fmaf(wr0.z, xc[2], a0); a1 = fmaf(sw2, xo[2], a1);
        a2 = fmaf(wr0.w, xc[3], a2); a3 = fmaf(sw3, xo[3], a3);
        a0 = fmaf(wr1.x, xc[4], a0); a1 = fmaf(sw4, xo[4], a1);
        a2 = fmaf(wr1.y, xc[5], a2); a3 = fmaf(sw5, xo[5], a3);
        a0 = fmaf(wr1.z, xc[6], a0); a1 = fmaf(sw6, xo[6], a1);
        a2 = fmaf(wr1.w, xc[7], a2); a3 = fmaf(sw7, xo[7], a3);
        const float z = (a0 + a1) + (a2 + a3);

        // z neighbors at +-1, +-2 (same component/column, zero-padded)
        float zv[5];
        zv[2] = z;
        float zm2 = __shfl_sync(FULL, z, cbase | ((i - 2) & 7));
        float zm1 = __shfl_sync(FULL, z, cbase | ((i - 1) & 7));
        float zp1 = __shfl_sync(FULL, z, cbase | ((i + 1) & 7));
        float zp2 = __shfl_sync(FULL, z, cbase | ((i + 2) & 7));
        zv[0] = (i >= 2) ? zm2 : 0.f;
        zv[1] = (i >= 1) ? zm1 : 0.f;
        zv[3] = (i <= 6) ? zp1 : 0.f;
        zv[4] = (i <= 5) ? zp2 : 0.f;

        // conv params (shared, broadcast LDS.128)
        const float4 wa  = *(const float4*)(s_c1w + s * 12);
        const float4 wb  = *(const float4*)(s_c1w + s * 12 + 4);
        const float4 wcv = *(const float4*)(s_c1w + s * 12 + 8);
        const float4 b1  = *(const float4*)(s_c1b + s * 4);
        const float4 va  = *(const float4*)(s_c2w + s * 12);
        const float4 vb  = *(const float4*)(s_c2w + s * 12 + 4);
        const float4 vc  = *(const float4*)(s_c2w + s * 12 + 8);
        const float  cb2 = s_misc[s * 2];
        const float  t   = s_misc[s * 2 + 1];

        const float k1[3][3] = {{wa.x, wa.y, wa.z},
                                {wa.w, wb.x, wb.y},
                                {wb.z, wb.w, wcv.x}};
        const float k2[3][3] = {{va.x, va.y, va.z},
                                {va.w, vb.x, vb.y},
                                {vb.z, vb.w, vc.x}};
        const float bb1[3] = {b1.x, b1.y, b1.z};

        // conv1 + soft at positions i-1, i, i+1 locally, then conv2 at i
        float o = cb2;
        #pragma unroll
        for (int p3 = 0; p3 < 3; p3++) {                 // pos = i-1+p3
            const bool valid = (p3 == 1) || ((p3 == 0) ? (i > 0) : (i < 7));
            #pragma unroll
            for (int ch = 0; ch < 3; ch++) {
                float v = bb1[ch];
                v = fmaf(k1[ch][0], zv[p3],     v);
                v = fmaf(k1[ch][1], zv[p3 + 1], v);
                v = fmaf(k1[ch][2], zv[p3 + 2], v);
                float st = fmaxf(v - t, 0.f) + fminf(v + t, 0.f);
                st = valid ? st : 0.f;                   // conv2 zero-padding
                o = fmaf(k2[ch][p3], st, o);
            }
        }
        x = o;
    }

    // out: x_r (8,64) then x_i (8,64); every lane owns a distinct (c,i,b)
    out[c * 512 + i * 64 + b] = x;
}

extern "C" void kernel_launch(void* const* d_in, const int* in_sizes, int n_in,
                              void* d_out, int out_size) {
    (void)in_sizes; (void)n_in; (void)out_size;
    const float* y_real  = (const float*)d_in[0];
    const float* y_imag  = (const float*)d_in[1];
    const float* w1_real = (const float*)d_in[2];
    const float* w1_imag = (const float*)d_in[3];
    const float* w2_real = (const float*)d_in[4];
    const float* w2_imag = (const float*)d_in[5];
    const float* thr     = (const float*)d_in[6];
    const float* c1w     = (const float*)d_in[7];
    const float* c1b     = (const float*)d_in[8];
    const float* c2w     = (const float*)d_in[9];
    const float* c2b     = (const float*)d_in[10];
    float* out = (float*)d_out;

    lista_kernel<<<16, 64>>>(y_real, y_imag, w1_real, w1_imag,
                             w2_real, w2_imag, thr, c1w, c1b, c2w, c2b, out);
}